// round 16
// baseline (speedup 1.0000x reference)
#include <cuda_runtime.h>
#include <cuda_fp16.h>
#include <cstdint>

#define IN_F    4096
#define OUT_F   14336
#define GROUPSZ 128
#define KROT    8
#define BATCH   16
#define NPAIR   (IN_F/2)         // 2048 pairs per layer
#define NPACKED (OUT_F/8)        // 1792 packed int32 cols
#define KSPLIT  8
#define KRANGE  (IN_F/KSPLIT)    // 512
#define TILE_K  32
#define NTILES  (KRANGE/TILE_K)  // 16
#define GRP_BLK (KRANGE/GROUPSZ) // 4 groups per block
#define NBLK    128              // output cols per block
#define NPACK_BLK 16
#define NBLOCKS (OUT_F/NBLK)     // 112
#define A_STRIDE (KRANGE+8)      // 520 halves
#define B_STRIDE (NBLK+8)        // 136 halves (272B = 17*16B)

#define ROT_T   1024             // rotate threads per block (32 warps)

// device scratch (no allocations allowed)
__device__ __align__(16) __half g_A[BATCH*IN_F];        // rotated+scaled, row-major
__device__ __align__(16) float  g_part[KSPLIT*BATCH*OUT_F];
__device__ unsigned g_cnt[NBLOCKS];                     // zero-init; self-resetting

union U32H2 { uint32_t u; __half2 h; };
__device__ __forceinline__ __half2 u2h(uint32_t v){ U32H2 x; x.u=v; return x.h; }
__device__ __forceinline__ uint32_t h2u(__half2 h){ U32H2 x; x.h=h; return x.u; }
__device__ __forceinline__ uint32_t extrA(uint32_t q){ return (q & 0x000F000Fu) | 0x64006400u; }
__device__ __forceinline__ uint32_t extrB(uint32_t q){ return (q & 0x00F000F0u) | 0x64006400u; }

// ---------------------------------------------------------------- rotate ----
// (unchanged: 9.25us measured)
__global__ __launch_bounds__(ROT_T) void rotate_kernel(
    const float* __restrict__ x,
    const float* __restrict__ theta,
    const int*   __restrict__ pairs,
    const float* __restrict__ csc)
{
    __shared__ __half2 sx[IN_F];                     // 16 KB
    const int tid = threadIdx.x;
    const int b2  = blockIdx.x;                      // 0..7
    const float* r0 = x + (size_t)(2*b2  )*IN_F;
    const float* r1 = x + (size_t)(2*b2+1)*IN_F;

    int2  pr[2];
    float th[2];
    #pragma unroll
    for (int p = 0; p < 2; p++) {
        int j = p*ROT_T + tid;
        pr[p] = reinterpret_cast<const int2*>(pairs)[j];
        th[p] = theta[j];
    }
    #pragma unroll
    for (int p = 0; p < IN_F/ROT_T; p++) {
        int c = p*ROT_T + tid;
        sx[c] = __halves2half2(__float2half(r0[c]), __float2half(r1[c]));
    }
    __syncthreads();

    for (int k = 0; k < KROT; k++) {
        __half2 C[2], S[2];
        #pragma unroll
        for (int p = 0; p < 2; p++) {
            float sf, cf; __sincosf(th[p], &sf, &cf);
            C[p] = __half2half2(__float2half(cf));
            S[p] = __half2half2(__float2half(sf));
        }
        int2 cur[2];
        #pragma unroll
        for (int p = 0; p < 2; p++) cur[p] = pr[p];
        if (k+1 < KROT) {
            #pragma unroll
            for (int p = 0; p < 2; p++) {
                int j = (k+1)*NPAIR + p*ROT_T + tid;
                pr[p] = reinterpret_cast<const int2*>(pairs)[j];
                th[p] = theta[j];
            }
        }
        #pragma unroll
        for (int p = 0; p < 2; p++) {
            __half2 a = sx[cur[p].x], bb = sx[cur[p].y];
            sx[cur[p].x] = __hsub2(__hmul2(C[p], a), __hmul2(S[p], bb));
            sx[cur[p].y] = __hadd2(__hmul2(S[p], a), __hmul2(C[p], bb));
        }
        __syncthreads();
    }

    __half2* oa = reinterpret_cast<__half2*>(g_A + (size_t)(2*b2  )*IN_F);
    __half2* ob = reinterpret_cast<__half2*>(g_A + (size_t)(2*b2+1)*IN_F);
    #pragma unroll
    for (int p = 0; p < IN_F/2/ROT_T; p++) {
        int i = p*ROT_T + tid;
        int c = 2*i;
        __half2 v0 = sx[c], v1 = sx[c+1];
        __half2 sc = __halves2half2(__float2half(csc[c]), __float2half(csc[c+1]));
        oa[i] = __hmul2(__lows2half2 (v0, v1), sc);
        ob[i] = __hmul2(__highs2half2(v0, v1), sc);
    }
}

// ------------------------------------------------------------------ gemm ----
// KSPLIT=8, 896 blocks x 256. Double-buffered sB + depth-2 qweight queue +
// ldmatrix/dequant/mma interleave. Last block per nb fuses the K reduction
// (fixed k-order -> bit-identical to the old reduce kernel).
__global__ __launch_bounds__(256) void gemm_kernel(
    const int*   __restrict__ qweight,
    const int*   __restrict__ qzeros,
    const float* __restrict__ scales,
    float*       __restrict__ out)
{
    __shared__ __half sA[BATCH*A_STRIDE];            // 16.25 KB
    __shared__ __half sB[2][TILE_K*B_STRIDE];        // 2 x 8.5 KB
    __shared__ uint4  lutZ[GRP_BLK*NPACK_BLK];       // 1 KB
    __shared__ uint4  lutS[GRP_BLK*NPACK_BLK];       // 1 KB
    __shared__ int    s_last;

    const int tid = threadIdx.x;
    const int nb  = blockIdx.x;
    const int ksp = blockIdx.y;
    const int kb0 = ksp * KRANGE;
    const int npb = nb * NPACK_BLK;

    // ---- load A slice [16][512] into padded shared
    for (int i = tid; i < BATCH*KRANGE/8; i += 256) {
        int r = i >> 6, c = i & 63;
        reinterpret_cast<uint4*>(sA + r*A_STRIDE)[c] =
            reinterpret_cast<const uint4*>(g_A + r*IN_F + kb0)[c];
    }
    // ---- zero/scale LUT (4 groups x 16 packs), magic-extract pair order
    if (tid < GRP_BLK*NPACK_BLK) {
        int g = tid >> 4, p = tid & 15;
        int gg = ksp*GRP_BLK + g;
        uint32_t zq  = (uint32_t)qzeros[gg*NPACKED + npb + p];
        uint32_t zq2 = zq >> 8;
        lutZ[tid] = make_uint4(extrA(zq), extrB(zq), extrA(zq2), extrB(zq2));
        const float* sp = scales + (size_t)gg*OUT_F + (npb+p)*8;
        float4 sv0 = reinterpret_cast<const float4*>(sp)[0];
        float4 sv1 = reinterpret_cast<const float4*>(sp)[1];
        __half2 six = __half2half2(__float2half(0.0625f));   // exact 1/16
        __half2 S0 = __halves2half2(__float2half(sv0.x), __float2half(sv1.x));
        __half2 S1 = __hmul2(__halves2half2(__float2half(sv0.y), __float2half(sv1.y)), six);
        __half2 S2 = __halves2half2(__float2half(sv0.z), __float2half(sv1.z));
        __half2 S3 = __hmul2(__halves2half2(__float2half(sv0.w), __float2half(sv1.w)), six);
        lutS[tid] = make_uint4(h2u(S0), h2u(S1), h2u(S2), h2u(S3));
    }
    __syncthreads();

    const int kl   = tid >> 3;             // dequant row 0..31
    const int pq   = (tid & 7) * 2;        // pack pair base
    const int warp = tid >> 5;
    const int lane = tid & 31;

    float acc[2][4];
    #pragma unroll
    for (int j=0;j<2;j++){ acc[j][0]=acc[j][1]=acc[j][2]=acc[j][3]=0.f; }

    const uint32_t sA_base  = (uint32_t)__cvta_generic_to_shared(sA);
    const uint32_t sB_base0 = (uint32_t)__cvta_generic_to_shared(sB[0]);
    const uint32_t sB_base1 = (uint32_t)__cvta_generic_to_shared(sB[1]);
    const uint32_t lrow  = lane & 15;
    const uint32_t lcol8 = (lane >> 4) << 3;
    const uint32_t aoff = (uint32_t)(lrow*A_STRIDE + lcol8) * 2u;
    const uint32_t boff = (uint32_t)(lrow*B_STRIDE + warp*16 + lcol8) * 2u;

    auto dequant = [&](int t, uint2 qv, __half* dst) {
        int g = t >> 2;
        uint32_t qq[2] = {qv.x, qv.y};
        #pragma unroll
        for (int u = 0; u < 2; u++) {
            int p = pq + u;
            uint4 zz = lutZ[g*16 + p];
            uint4 ss = lutS[g*16 + p];
            uint32_t qu  = qq[u];
            uint32_t qu2 = qu >> 8;
            __half2 w0 = __hmul2(__hsub2(u2h(extrA(qu )), u2h(zz.x)), u2h(ss.x));
            __half2 w1 = __hmul2(__hsub2(u2h(extrB(qu )), u2h(zz.y)), u2h(ss.y));
            __half2 w2 = __hmul2(__hsub2(u2h(extrA(qu2)), u2h(zz.z)), u2h(ss.z));
            __half2 w3 = __hmul2(__hsub2(u2h(extrB(qu2)), u2h(zz.w)), u2h(ss.w));
            __half2 n01 = __lows2half2 (w0, w1);
            __half2 n23 = __lows2half2 (w2, w3);
            __half2 n45 = __highs2half2(w0, w1);
            __half2 n67 = __highs2half2(w2, w3);
            reinterpret_cast<uint4*>(dst + kl*B_STRIDE + p*8)[0] =
                make_uint4(h2u(n01), h2u(n23), h2u(n45), h2u(n67));
        }
    };
    auto ldq = [&](int t) {
        return reinterpret_cast<const uint2*>(
            qweight + (size_t)(kb0 + t*TILE_K + kl)*NPACKED + npb + pq)[0];
    };

    // ---- prologue: depth-2 queue. qA = data(t+1), qB = data(t+2)
    uint2 q0 = ldq(0);
    uint2 qA = ldq(1);
    uint2 qB = ldq(2);
    dequant(0, q0, sB[0]);
    __syncthreads();

    #pragma unroll 2
    for (int t = 0; t < NTILES; t++) {
        const uint32_t bbase = (t & 1) ? sB_base1 : sB_base0;
        // frags kk=0 first; their latency hides under dequant ALU
        uint32_t a0,a1,a2,a3, b0,b1,b2,b3;
        uint32_t aaddr0 = sA_base + aoff + (uint32_t)(t*TILE_K)*2u;
        asm volatile("ldmatrix.sync.aligned.m8n8.x4.shared.b16 {%0,%1,%2,%3}, [%4];"
            : "=r"(a0),"=r"(a1),"=r"(a2),"=r"(a3) : "r"(aaddr0));
        asm volatile("ldmatrix.sync.aligned.m8n8.x4.trans.shared.b16 {%0,%1,%2,%3}, [%4];"
            : "=r"(b0),"=r"(b1),"=r"(b2),"=r"(b3) : "r"(bbase + boff));

        if (t + 1 < NTILES) dequant(t+1, qA, sB[(t+1)&1]);
        qA = qB;
        if (t + 3 < NTILES) qB = ldq(t+3);

        asm volatile("mma.sync.aligned.m16n8k16.row.col.f32.f16.f16.f32 "
            "{%0,%1,%2,%3}, {%4,%5,%6,%7}, {%8,%9}, {%0,%1,%2,%3};"
            : "+f"(acc[0][0]),"+f"(acc[0][1]),"+f"(acc[0][2]),"+f"(acc[0][3])
            : "r"(a0),"r"(a1),"r"(a2),"r"(a3),"r"(b0),"r"(b1));
        asm volatile("mma.sync.aligned.m16n8k16.row.col.f32.f16.f16.f32 "
            "{%0,%1,%2,%3}, {%4,%5,%6,%7}, {%8,%9}, {%0,%1,%2,%3};"
            : "+f"(acc[1][0]),"+f"(acc[1][1]),"+f"(acc[1][2]),"+f"(acc[1][3])
            : "r"(a0),"r"(a1),"r"(a2),"r"(a3),"r"(b2),"r"(b3));

        // frags kk=1
        uint32_t aaddr1 = aaddr0 + 16*2u;
        asm volatile("ldmatrix.sync.aligned.m8n8.x4.shared.b16 {%0,%1,%2,%3}, [%4];"
            : "=r"(a0),"=r"(a1),"=r"(a2),"=r"(a3) : "r"(aaddr1));
        asm volatile("ldmatrix.sync.aligned.m8n8.x4.trans.shared.b16 {%0,%1,%2,%3}, [%4];"
            : "=r"(b0),"=r"(b1),"=r"(b2),"=r"(b3) : "r"(bbase + boff + (uint32_t)(16*B_STRIDE)*2u));
        asm volatile("mma.sync.aligned.m16n8k16.row.col.f32.f16.f16.f32 "
            "{%0,%1,%2,%3}, {%4,%5,%6,%7}, {%8,%9}, {%0,%1,%2,%3};"
            : "+f"(acc[0][0]),"+f"(acc[0][1]),"+f"(acc[0][2]),"+f"(acc[0][3])
            : "r"(a0),"r"(a1),"r"(a2),"r"(a3),"r"(b0),"r"(b1));
        asm volatile("mma.sync.aligned.m16n8k16.row.col.f32.f16.f16.f32 "
            "{%0,%1,%2,%3}, {%4,%5,%6,%7}, {%8,%9}, {%0,%1,%2,%3};"
            : "+f"(acc[1][0]),"+f"(acc[1][1]),"+f"(acc[1][2]),"+f"(acc[1][3])
            : "r"(a0),"r"(a1),"r"(a2),"r"(a3),"r"(b2),"r"(b3));

        if (t + 1 < NTILES) __syncthreads();
    }

    // ---- store fp32 partials
    const int g8 = lane >> 2;
    const int t4 = lane & 3;
    float* outp = g_part + (size_t)ksp*BATCH*OUT_F;
    #pragma unroll
    for (int j = 0; j < 2; j++) {
        int col = nb*NBLK + warp*16 + j*8 + 2*t4;
        outp[(size_t)g8*OUT_F     + col    ] = acc[j][0];
        outp[(size_t)g8*OUT_F     + col + 1] = acc[j][1];
        outp[(size_t)(g8+8)*OUT_F + col    ] = acc[j][2];
        outp[(size_t)(g8+8)*OUT_F + col + 1] = acc[j][3];
    }

    // ---- fused reduction: last block for this nb sums all KSPLIT slices
    __threadfence();
    __syncthreads();
    if (tid == 0) {
        unsigned old = atomicAdd(&g_cnt[nb], 1u);
        s_last = (old == KSPLIT - 1);
    }
    __syncthreads();
    if (s_last) {
        // deterministic fixed k-order sum, identical to the old reduce kernel
        for (int i = tid; i < BATCH*NBLK/2; i += 256) {
            int r  = i >> 6;                 // row 0..15
            int c2 = i & 63;                 // float2 col within nb block
            size_t off = (size_t)r*OUT_F + nb*NBLK + 2*c2;
            float2 s = make_float2(0.f, 0.f);
            #pragma unroll
            for (int k = 0; k < KSPLIT; k++) {
                float2 v = *reinterpret_cast<const float2*>(g_part + (size_t)k*BATCH*OUT_F + off);
                s.x += v.x; s.y += v.y;
            }
            float2 rr;
            rr.x = __half2float(__float2half_rn(s.x));
            rr.y = __half2float(__float2half_rn(s.y));
            *reinterpret_cast<float2*>(out + off) = rr;
        }
        __syncthreads();
        if (tid == 0) g_cnt[nb] = 0;         // self-reset for next replay
    }
}

// ---------------------------------------------------------------- launch ----
extern "C" void kernel_launch(void* const* d_in, const int* in_sizes, int n_in,
                              void* d_out, int out_size)
{
    const float* x     = (const float*)d_in[0];
    const float* theta = (const float*)d_in[1];
    const int*   pairs = (const int*)  d_in[2];
    const float* csc   = (const float*)d_in[3];
    const int*   qw    = (const int*)  d_in[4];
    const int*   qz    = (const int*)  d_in[5];
    const float* sc    = (const float*)d_in[6];
    (void)in_sizes; (void)n_in; (void)out_size;

    rotate_kernel<<<BATCH/2, ROT_T>>>(x, theta, pairs, csc);
    gemm_kernel<<<dim3(NBLOCKS, KSPLIT), 256>>>(qw, qz, sc, (float*)d_out);
}

// round 17
// speedup vs baseline: 1.3754x; 1.3754x over previous
#include <cuda_runtime.h>
#include <cuda_fp16.h>
#include <cstdint>

#define IN_F    4096
#define OUT_F   14336
#define GROUPSZ 128
#define KROT    8
#define BATCH   16
#define NPAIR   (IN_F/2)         // 2048 pairs per layer
#define NPACKED (OUT_F/8)        // 1792 packed int32 cols
#define KSPLIT  8
#define KRANGE  (IN_F/KSPLIT)    // 512
#define GRP_BLK (KRANGE/GROUPSZ) // 4 groups per slice
#define NBLK    128              // output cols per block
#define NPACK_BLK 16
#define NBLOCKS (OUT_F/NBLK)     // 112
#define A_STRIDE (KRANGE+8)      // 520 halves (4-word row offset -> cf ldmatrix)
#define RQ_ROWS 256              // raw-q staging rows per half
#define RQ_PAD  20               // 16 packs + 4 pad words (80B, 16B aligned)

#define ROT_T   1024

// device scratch (no allocations allowed)
__device__ __align__(16) __half g_A[BATCH*IN_F];
__device__ __align__(16) float  g_part[KSPLIT*BATCH*OUT_F];
__device__ unsigned g_cnt[NBLOCKS];                 // zero-init; self-resetting

union U32H2 { uint32_t u; __half2 h; };
__device__ __forceinline__ __half2 u2h(uint32_t v){ U32H2 x; x.u=v; return x.h; }
__device__ __forceinline__ uint32_t h2u(__half2 h){ U32H2 x; x.h=h; return x.u; }

// ---------------------------------------------------------------- rotate ----
// (unchanged: 9.25us measured)
__global__ __launch_bounds__(ROT_T) void rotate_kernel(
    const float* __restrict__ x,
    const float* __restrict__ theta,
    const int*   __restrict__ pairs,
    const float* __restrict__ csc)
{
    __shared__ __half2 sx[IN_F];
    const int tid = threadIdx.x;
    const int b2  = blockIdx.x;
    const float* r0 = x + (size_t)(2*b2  )*IN_F;
    const float* r1 = x + (size_t)(2*b2+1)*IN_F;

    int2  pr[2];
    float th[2];
    #pragma unroll
    for (int p = 0; p < 2; p++) {
        int j = p*ROT_T + tid;
        pr[p] = reinterpret_cast<const int2*>(pairs)[j];
        th[p] = theta[j];
    }
    #pragma unroll
    for (int p = 0; p < IN_F/ROT_T; p++) {
        int c = p*ROT_T + tid;
        sx[c] = __halves2half2(__float2half(r0[c]), __float2half(r1[c]));
    }
    __syncthreads();

    for (int k = 0; k < KROT; k++) {
        __half2 C[2], S[2];
        #pragma unroll
        for (int p = 0; p < 2; p++) {
            float sf, cf; __sincosf(th[p], &sf, &cf);
            C[p] = __half2half2(__float2half(cf));
            S[p] = __half2half2(__float2half(sf));
        }
        int2 cur[2];
        #pragma unroll
        for (int p = 0; p < 2; p++) cur[p] = pr[p];
        if (k+1 < KROT) {
            #pragma unroll
            for (int p = 0; p < 2; p++) {
                int j = (k+1)*NPAIR + p*ROT_T + tid;
                pr[p] = reinterpret_cast<const int2*>(pairs)[j];
                th[p] = theta[j];
            }
        }
        #pragma unroll
        for (int p = 0; p < 2; p++) {
            __half2 a = sx[cur[p].x], bb = sx[cur[p].y];
            sx[cur[p].x] = __hsub2(__hmul2(C[p], a), __hmul2(S[p], bb));
            sx[cur[p].y] = __hadd2(__hmul2(S[p], a), __hmul2(C[p], bb));
        }
        __syncthreads();
    }

    __half2* oa = reinterpret_cast<__half2*>(g_A + (size_t)(2*b2  )*IN_F);
    __half2* ob = reinterpret_cast<__half2*>(g_A + (size_t)(2*b2+1)*IN_F);
    #pragma unroll
    for (int p = 0; p < IN_F/2/ROT_T; p++) {
        int i = p*ROT_T + tid;
        int c = 2*i;
        __half2 v0 = sx[c], v1 = sx[c+1];
        __half2 sc = __halves2half2(__float2half(csc[c]), __float2half(csc[c+1]));
        oa[i] = __hmul2(__lows2half2 (v0, v1), sc);
        ob[i] = __hmul2(__highs2half2(v0, v1), sc);
    }
}

// ------------------------------------------------------------------ gemm ----
// Register-direct B dequant: raw packed qweight staged in smem (coalesced),
// read back via broadcast LDS.64, nibbles extracted straight into mma fragment
// registers. No dequant STS, no B ldmatrix, no LUTs, 3 barriers total.
__global__ __launch_bounds__(256) void gemm_kernel(
    const int*   __restrict__ qweight,
    const int*   __restrict__ qzeros,
    const float* __restrict__ scales,
    float*       __restrict__ out)
{
    __shared__ __half    sA[BATCH*A_STRIDE];        // 16.6 KB
    __shared__ uint32_t  rawQ[RQ_ROWS*RQ_PAD];      // 20 KB
    __shared__ int       s_last;

    const int tid = threadIdx.x;
    const int nb  = blockIdx.x;
    const int ksp = blockIdx.y;
    const int kb0 = ksp * KRANGE;
    const int npb = nb * NPACK_BLK;

    const int warp = tid >> 5;
    const int lane = tid & 31;
    const int g8   = lane >> 2;            // fragment col within 8
    const int t4   = lane & 3;             // fragment row group
    const uint32_t sh4 = 4u*(uint32_t)g8;  // nibble shift for col g8

    // ---- load A slice [16][512] into padded shared
    for (int i = tid; i < BATCH*KRANGE/8; i += 256) {
        int r = i >> 6, c = i & 63;
        reinterpret_cast<uint4*>(sA + r*A_STRIDE)[c] =
            reinterpret_cast<const uint4*>(g_A + r*IN_F + kb0)[c];
    }

    // ---- per-thread zero-magic / scale registers: 4 groups x 2 packs
    uint32_t zmag[GRP_BLK][2], smul[GRP_BLK][2];
    #pragma unroll
    for (int g = 0; g < GRP_BLK; g++) {
        int gg = ksp*GRP_BLK + g;
        #pragma unroll
        for (int j = 0; j < 2; j++) {
            uint32_t zq = (uint32_t)qzeros[gg*NPACKED + npb + 2*warp + j];
            uint32_t zm = 0x6400u + ((zq >> sh4) & 15u);
            zmag[g][j] = zm | (zm << 16);
            float sf = scales[(size_t)gg*OUT_F + nb*NBLK + warp*16 + j*8 + g8];
            smul[g][j] = h2u(__half2half2(__float2half(sf)));
        }
    }

    float acc[2][4];
    #pragma unroll
    for (int j=0;j<2;j++){ acc[j][0]=acc[j][1]=acc[j][2]=acc[j][3]=0.f; }

    const uint32_t sA_base = (uint32_t)__cvta_generic_to_shared(sA);
    const uint32_t rq_base = (uint32_t)__cvta_generic_to_shared(rawQ);
    const uint32_t aoff = (uint32_t)((lane&15)*A_STRIDE + ((lane>>4)<<3)) * 2u;
    const uint32_t qoff = (uint32_t)(2*t4*RQ_PAD + 2*warp) * 4u;  // row 2t4, packs 2w

    #pragma unroll
    for (int h = 0; h < 2; h++) {
        if (h) __syncthreads();            // protect rawQ reuse
        // ---- stage raw qweight half: 256 rows x 64B, coalesced
        #pragma unroll
        for (int p = 0; p < 4; p++) {
            int idx = p*256 + tid;
            int row = idx >> 2, c4 = idx & 3;
            uint4 v = *reinterpret_cast<const uint4*>(
                qweight + (size_t)(kb0 + h*RQ_ROWS + row)*NPACKED + npb + c4*4);
            *reinterpret_cast<uint4*>(rawQ + row*RQ_PAD + c4*4) = v;
        }
        __syncthreads();

        #pragma unroll
        for (int st = 0; st < 16; st++) {
            const int g = (h*16 + st) >> 3;      // quant group (compile-time)
            // A fragments
            uint32_t a0,a1,a2,a3;
            uint32_t aaddr = sA_base + aoff + (uint32_t)((h*RQ_ROWS + st*16)*2);
            asm volatile("ldmatrix.sync.aligned.m8n8.x4.shared.b16 {%0,%1,%2,%3}, [%4];"
                : "=r"(a0),"=r"(a1),"=r"(a2),"=r"(a3) : "r"(aaddr));
            // raw q words: rows st*16 + {2t4, 2t4+1, 2t4+8, 2t4+9}, packs {2w,2w+1}
            uint32_t base = rq_base + (uint32_t)(st*16*RQ_PAD)*4u + qoff;
            uint2 qa, qb, qc, qd;
            asm volatile("ld.shared.v2.u32 {%0,%1}, [%2];" : "=r"(qa.x),"=r"(qa.y) : "r"(base));
            asm volatile("ld.shared.v2.u32 {%0,%1}, [%2];" : "=r"(qb.x),"=r"(qb.y) : "r"(base + RQ_PAD*4u));
            asm volatile("ld.shared.v2.u32 {%0,%1}, [%2];" : "=r"(qc.x),"=r"(qc.y) : "r"(base + 8u*RQ_PAD*4u));
            asm volatile("ld.shared.v2.u32 {%0,%1}, [%2];" : "=r"(qd.x),"=r"(qd.y) : "r"(base + 9u*RQ_PAD*4u));
            #pragma unroll
            for (int j = 0; j < 2; j++) {
                uint32_t wa = j ? qa.y : qa.x;
                uint32_t wb = j ? qb.y : qb.x;
                uint32_t wc = j ? qc.y : qc.x;
                uint32_t wd = j ? qd.y : qd.x;
                // extract (1024+nib) pairs: {rowA,rowB} packed as fp16x2
                uint32_t e0 = ((wa >> sh4) & 15u) | 0x6400u;
                uint32_t e1 = ((wb >> sh4) & 15u) | 0x6400u;
                uint32_t e2 = ((wc >> sh4) & 15u) | 0x6400u;
                uint32_t e3 = ((wd >> sh4) & 15u) | 0x6400u;
                uint32_t f0 = __byte_perm(e0, e1, 0x5410);
                uint32_t f1 = __byte_perm(e2, e3, 0x5410);
                // exact (nib - z) then single-rounded * s : matches reference
                uint32_t b0 = h2u(__hmul2(__hsub2(u2h(f0), u2h(zmag[g][j])), u2h(smul[g][j])));
                uint32_t b1 = h2u(__hmul2(__hsub2(u2h(f1), u2h(zmag[g][j])), u2h(smul[g][j])));
                asm volatile("mma.sync.aligned.m16n8k16.row.col.f32.f16.f16.f32 "
                    "{%0,%1,%2,%3}, {%4,%5,%6,%7}, {%8,%9}, {%0,%1,%2,%3};"
                    : "+f"(acc[j][0]),"+f"(acc[j][1]),"+f"(acc[j][2]),"+f"(acc[j][3])
                    : "r"(a0),"r"(a1),"r"(a2),"r"(a3),"r"(b0),"r"(b1));
            }
        }
    }

    // ---- store fp32 partials
    float* outp = g_part + (size_t)ksp*BATCH*OUT_F;
    #pragma unroll
    for (int j = 0; j < 2; j++) {
        int col = nb*NBLK + warp*16 + j*8 + 2*t4;
        outp[(size_t)g8*OUT_F     + col    ] = acc[j][0];
        outp[(size_t)g8*OUT_F     + col + 1] = acc[j][1];
        outp[(size_t)(g8+8)*OUT_F + col    ] = acc[j][2];
        outp[(size_t)(g8+8)*OUT_F + col + 1] = acc[j][3];
    }

    // ---- fused reduction: last block for this nb sums all KSPLIT slices
    __threadfence();
    __syncthreads();
    if (tid == 0) {
        unsigned old = atomicAdd(&g_cnt[nb], 1u);
        s_last = (old == KSPLIT - 1);
    }
    __syncthreads();
    if (s_last) {
        for (int i = tid; i < BATCH*NBLK/2; i += 256) {
            int r  = i >> 6;
            int c2 = i & 63;
            size_t off = (size_t)r*OUT_F + nb*NBLK + 2*c2;
            float2 s = make_float2(0.f, 0.f);
            #pragma unroll
            for (int k = 0; k < KSPLIT; k++) {
                float2 v = *reinterpret_cast<const float2*>(g_part + (size_t)k*BATCH*OUT_F + off);
                s.x += v.x; s.y += v.y;
            }
            float2 rr;
            rr.x = __half2float(__float2half_rn(s.x));
            rr.y = __half2float(__float2half_rn(s.y));
            *reinterpret_cast<float2*>(out + off) = rr;
        }
        __syncthreads();
        if (tid == 0) g_cnt[nb] = 0;
    }
}

// ---------------------------------------------------------------- launch ----
extern "C" void kernel_launch(void* const* d_in, const int* in_sizes, int n_in,
                              void* d_out, int out_size)
{
    const float* x     = (const float*)d_in[0];
    const float* theta = (const float*)d_in[1];
    const int*   pairs = (const int*)  d_in[2];
    const float* csc   = (const float*)d_in[3];
    const int*   qw    = (const int*)  d_in[4];
    const int*   qz    = (const int*)  d_in[5];
    const float* sc    = (const float*)d_in[6];
    (void)in_sizes; (void)n_in; (void)out_size;

    rotate_kernel<<<BATCH/2, ROT_T>>>(x, theta, pairs, csc);
    gemm_kernel<<<dim3(NBLOCKS, KSPLIT), 256>>>(qw, qz, sc, (float*)d_out);
}